// round 3
// baseline (speedup 1.0000x reference)
#include <cuda_runtime.h>

#define B_  8
#define C_  512
#define N_  1024
#define NH  8
#define CH  64
#define G_  32
#define CPG 16
#define EPS 1e-5f

// ---------------- static scratch (no allocations allowed) ----------------
__device__ float g_hn  [(long long)B_ * C_ * N_];        // 16 MB
__device__ float g_qkv [(long long)B_ * 3 * C_ * N_];    // 48 MB
__device__ float g_att [(long long)B_ * C_ * N_];        // 16 MB
__device__ float g_proj[(long long)B_ * C_ * N_];        // 16 MB

// ---------------- generic tiled fp32 GEMM ----------------
// C[m][n] = alpha * sum_k A[m][k]*B[k][n] (+ bias[m]);  A row-major [M][K], B row-major [K][N]
template<int BM, int BN, int TM, int TN, bool HASB>
__global__ __launch_bounds__(256) void gemm_k(
    const float* __restrict__ A, const float* __restrict__ Bm,
    float* __restrict__ Cm, const float* __restrict__ bias,
    int K, int lda, int ldb, int ldc,
    long long sA, long long sB, long long sC, float alpha)
{
    constexpr int BK = 16;
    __shared__ float As[BK][BM + 4];
    __shared__ float Bs[BK][BN + 4];

    A  += (long long)blockIdx.z * sA;
    Bm += (long long)blockIdx.z * sB;
    Cm += (long long)blockIdx.z * sC;

    const int m0  = blockIdx.y * BM;
    const int n0  = blockIdx.x * BN;
    const int tid = threadIdx.x;
    const int tx  = tid % (BN / TN);
    const int ty  = tid / (BN / TN);

    float acc[TM][TN];
#pragma unroll
    for (int i = 0; i < TM; i++)
#pragma unroll
        for (int j = 0; j < TN; j++) acc[i][j] = 0.f;

    for (int k0 = 0; k0 < K; k0 += BK) {
        // A tile -> As[k][m]   (4 threads per m-row, 64 rows/pass)
        {
            constexpr int TPR = BK / 4;
            constexpr int RPP = 256 / TPR;
#pragma unroll
            for (int p = 0; p < BM / RPP; p++) {
                int m = tid / TPR + p * RPP;
                int k = (tid % TPR) * 4;
                float4 v = *(const float4*)(A + (long long)(m0 + m) * lda + k0 + k);
                As[k + 0][m] = v.x; As[k + 1][m] = v.y;
                As[k + 2][m] = v.z; As[k + 3][m] = v.w;
            }
        }
        // B tile -> Bs[k][n]
        {
            constexpr int TPR = BN / 4;
            constexpr int RPP = 256 / TPR;
#pragma unroll
            for (int p = 0; p < BK / RPP; p++) {
                int k = tid / TPR + p * RPP;
                int n = (tid % TPR) * 4;
                float4 v = *(const float4*)(Bm + (long long)(k0 + k) * ldb + n0 + n);
                *(float4*)&Bs[k][n] = v;
            }
        }
        __syncthreads();

#pragma unroll
        for (int k = 0; k < BK; k++) {
            float a[TM], bv[TN];
#pragma unroll
            for (int i = 0; i < TM; i++) a[i] = As[k][ty * TM + i];
#pragma unroll
            for (int j = 0; j < TN; j++) bv[j] = Bs[k][tx * TN + j];
#pragma unroll
            for (int i = 0; i < TM; i++)
#pragma unroll
                for (int j = 0; j < TN; j++) acc[i][j] += a[i] * bv[j];
        }
        __syncthreads();
    }

#pragma unroll
    for (int i = 0; i < TM; i++) {
        int m = m0 + ty * TM + i;
        float bi = HASB ? bias[m] : 0.f;
#pragma unroll
        for (int j0 = 0; j0 < TN; j0 += 4) {
            float4 o;
            o.x = alpha * acc[i][j0 + 0] + bi;
            o.y = alpha * acc[i][j0 + 1] + bi;
            o.z = alpha * acc[i][j0 + 2] + bi;
            o.w = alpha * acc[i][j0 + 3] + bi;
            *(float4*)(Cm + (long long)m * ldc + n0 + tx * TN + j0) = o;
        }
    }
}

// ---------------- fused flash attention ----------------
// qkv per (b,h): q at +0, k at +64*N, v at +128*N, slice stride 192*N, each [64][N].
// Computes att[bh][c][t] = sum_s softmax_s(0.125 * q^T k)[t][s] * v[c][s].
// Block: 64 t-rows (blockIdx.x), one bh (blockIdx.y). 256 threads, 4x4 microtiles.
__global__ __launch_bounds__(256) void flash_k(
    const float* __restrict__ qkv, float* __restrict__ att)
{
    extern __shared__ float smem[];
    float (*Qs)[68]  = (float(*)[68])(smem);                 // [c][t]
    float (*Ks)[68]  = (float(*)[68])(smem + 64 * 68);       // [c][s]
    float (*Ps)[68]  = (float(*)[68])(smem + 2 * 64 * 68);   // [t][s]
    float (*Vts)[65] = (float(*)[65])(smem + 3 * 64 * 68);   // [s][c]

    const int bh = blockIdx.y;
    const int t0 = blockIdx.x * 64;
    const float* q = qkv + (long long)bh * 192 * N_;
    const float* k = q + 64 * N_;
    const float* v = q + 128 * N_;

    const int tid = threadIdx.x;
    const int tx  = tid & 15;       // 16 groups x 4 = 64 (s or c dim)
    const int ty  = tid >> 4;       // 16 groups x 4 = 64 (t dim)

    // load Q tile: Qs[c][t]
#pragma unroll
    for (int p = 0; p < 4; p++) {
        int c = (tid >> 4) + p * 16;
        *(float4*)&Qs[c][(tid & 15) * 4] =
            *(const float4*)(q + (long long)c * N_ + t0 + (tid & 15) * 4);
    }

    float m[4], l[4], O[4][4];
#pragma unroll
    for (int i = 0; i < 4; i++) {
        m[i] = -1e30f; l[i] = 0.f;
#pragma unroll
        for (int j = 0; j < 4; j++) O[i][j] = 0.f;
    }

    for (int s0 = 0; s0 < N_; s0 += 64) {
        __syncthreads();   // previous PV reads done before overwriting Ks/Vts
#pragma unroll
        for (int p = 0; p < 4; p++) {
            int c = (tid >> 4) + p * 16;
            int s = (tid & 15) * 4;
            *(float4*)&Ks[c][s] = *(const float4*)(k + (long long)c * N_ + s0 + s);
            float4 vv = *(const float4*)(v + (long long)c * N_ + s0 + s);
            Vts[s + 0][c] = vv.x; Vts[s + 1][c] = vv.y;
            Vts[s + 2][c] = vv.z; Vts[s + 3][c] = vv.w;
        }
        __syncthreads();

        // S = q^T k  (64x64 tile, 4x4 per thread)
        float S[4][4];
#pragma unroll
        for (int i = 0; i < 4; i++)
#pragma unroll
            for (int j = 0; j < 4; j++) S[i][j] = 0.f;
#pragma unroll 8
        for (int c = 0; c < 64; c++) {
            float4 a = *(float4*)&Qs[c][ty * 4];
            float4 b = *(float4*)&Ks[c][tx * 4];
            float av[4] = {a.x, a.y, a.z, a.w};
            float bv[4] = {b.x, b.y, b.z, b.w};
#pragma unroll
            for (int i = 0; i < 4; i++)
#pragma unroll
                for (int j = 0; j < 4; j++) S[i][j] += av[i] * bv[j];
        }

        // online softmax update (rows = t, reduce across 16 tx lanes)
#pragma unroll
        for (int i = 0; i < 4; i++) {
            float rm = fmaxf(fmaxf(S[i][0], S[i][1]), fmaxf(S[i][2], S[i][3])) * 0.125f;
#pragma unroll
            for (int off = 8; off; off >>= 1)
                rm = fmaxf(rm, __shfl_xor_sync(0xffffffffu, rm, off));
            float mn = fmaxf(m[i], rm);
            float resc = __expf(m[i] - mn);
            float rs = 0.f;
#pragma unroll
            for (int j = 0; j < 4; j++) {
                float p = __expf(S[i][j] * 0.125f - mn);
                S[i][j] = p;                 // reuse S as P
                rs += p;
            }
#pragma unroll
            for (int off = 8; off; off >>= 1)
                rs += __shfl_xor_sync(0xffffffffu, rs, off);
            l[i] = l[i] * resc + rs;
            m[i] = mn;
#pragma unroll
            for (int j = 0; j < 4; j++) O[i][j] *= resc;
            *(float4*)&Ps[ty * 4 + i][tx * 4] = make_float4(S[i][0], S[i][1], S[i][2], S[i][3]);
        }
        __syncthreads();

        // O += P * V^T : O[t][c] += sum_s Ps[t][s] * Vts[s][c]
#pragma unroll 8
        for (int s = 0; s < 64; s++) {
            float a[4], bv[4];
#pragma unroll
            for (int i = 0; i < 4; i++) a[i] = Ps[ty * 4 + i][s];
#pragma unroll
            for (int j = 0; j < 4; j++) bv[j] = Vts[s][tx * 4 + j];
#pragma unroll
            for (int i = 0; i < 4; i++)
#pragma unroll
                for (int j = 0; j < 4; j++) O[i][j] += a[i] * bv[j];
        }
    }

    // normalize + store: att[bh][c][t], c = tx*4+j, t = t0 + ty*4 + i
    float inv[4];
#pragma unroll
    for (int i = 0; i < 4; i++) inv[i] = 1.f / l[i];
    float* ab = att + (long long)bh * CH * N_;
#pragma unroll
    for (int j = 0; j < 4; j++) {
        float4 o = make_float4(O[0][j] * inv[0], O[1][j] * inv[1],
                               O[2][j] * inv[2], O[3][j] * inv[3]);
        *(float4*)(ab + (long long)(tx * 4 + j) * N_ + t0 + ty * 4) = o;
    }
}

// ---------------- GroupNorm (optionally + residual) ----------------
template<bool RES>
__global__ __launch_bounds__(256) void gn_k(
    const float* __restrict__ in, const float* __restrict__ scale,
    const float* __restrict__ bias, const float* __restrict__ resid,
    float* __restrict__ out)
{
    const int bg = blockIdx.x;
    const int g  = bg % G_;
    const long long base = (long long)bg * CPG * N_;
    const float4* p = (const float4*)(in + base);
    const int tid = threadIdx.x;

    float s = 0.f, ss = 0.f;
    float4 loc[16];
#pragma unroll
    for (int qq = 0; qq < 16; qq++) {
        float4 v = p[tid + qq * 256];
        loc[qq] = v;
        s  += v.x + v.y + v.z + v.w;
        ss += v.x * v.x + v.y * v.y + v.z * v.z + v.w * v.w;
    }
#pragma unroll
    for (int off = 16; off; off >>= 1) {
        s  += __shfl_xor_sync(0xffffffffu, s,  off);
        ss += __shfl_xor_sync(0xffffffffu, ss, off);
    }
    __shared__ float sm[8], sm2[8];
    __shared__ float s_mu, s_r;
    if ((tid & 31) == 0) { sm[tid >> 5] = s; sm2[tid >> 5] = ss; }
    __syncthreads();
    if (tid == 0) {
        float ts = 0.f, tss = 0.f;
#pragma unroll
        for (int i = 0; i < 8; i++) { ts += sm[i]; tss += sm2[i]; }
        float mu  = ts / 16384.f;
        float var = tss / 16384.f - mu * mu;
        s_mu = mu;
        s_r  = rsqrtf(var + EPS);
    }
    __syncthreads();
    const float mu = s_mu, r = s_r;

#pragma unroll
    for (int qq = 0; qq < 16; qq++) {
        int idx = tid + qq * 256;
        int c   = g * CPG + (idx >> 8);
        float sc = scale[c] * r;
        float bi = bias[c] - mu * sc;
        float4 v = loc[qq], o;
        o.x = v.x * sc + bi; o.y = v.y * sc + bi;
        o.z = v.z * sc + bi; o.w = v.w * sc + bi;
        if (RES) {
            float4 rv = ((const float4*)(resid + base))[idx];
            o.x += rv.x; o.y += rv.y; o.z += rv.z; o.w += rv.w;
        }
        ((float4*)(out + base))[idx] = o;
    }
}

// ---------------- launch ----------------
extern "C" void kernel_launch(void* const* d_in, const int* in_sizes, int n_in,
                              void* d_out, int out_size)
{
    const float* x      = (const float*)d_in[0];
    const float* gn1_s  = (const float*)d_in[1];
    const float* gn1_b  = (const float*)d_in[2];
    const float* w_qkv  = (const float*)d_in[3];
    const float* b_qkv  = (const float*)d_in[4];
    const float* w_proj = (const float*)d_in[5];
    const float* b_proj = (const float*)d_in[6];
    const float* gn2_s  = (const float*)d_in[7];
    const float* gn2_b  = (const float*)d_in[8];
    float* out = (float*)d_out;

    float *hn, *qkv, *att, *proj;
    cudaGetSymbolAddress((void**)&hn,   g_hn);
    cudaGetSymbolAddress((void**)&qkv,  g_qkv);
    cudaGetSymbolAddress((void**)&att,  g_att);
    cudaGetSymbolAddress((void**)&proj, g_proj);

    const int flash_smem = (3 * 64 * 68 + 64 * 65) * 4;   // 68864 B
    cudaFuncSetAttribute(flash_k, cudaFuncAttributeMaxDynamicSharedMemorySize, flash_smem);

    // 1) hn = GroupNorm(x)
    gn_k<false><<<B_ * G_, 256>>>(x, gn1_s, gn1_b, nullptr, hn);

    // 2) qkv[b,o,n] = w_qkv[o,:] . hn[b,:,n] + b_qkv[o]
    gemm_k<128, 128, 8, 8, true><<<dim3(N_ / 128, 1536 / 128, B_), 256>>>(
        w_qkv, hn, qkv, b_qkv, C_, C_, N_, N_,
        0LL, (long long)C_ * N_, (long long)3 * C_ * N_, 1.f);

    // 3) fused attention per (b,h)
    flash_k<<<dim3(N_ / 64, B_ * NH), 256, flash_smem>>>(qkv, att);

    // 4) proj[b,o,n] = w_proj[o,:] . att[b,:,n] + b_proj[o]
    gemm_k<128, 128, 8, 8, true><<<dim3(N_ / 128, C_ / 128, B_), 256>>>(
        w_proj, att, proj, b_proj, C_, C_, N_, N_,
        0LL, (long long)C_ * N_, (long long)C_ * N_, 1.f);

    // 5) out = x + GroupNorm(proj)
    gn_k<true><<<B_ * G_, 256>>>(proj, gn2_s, gn2_b, x, out);
}

// round 6
// speedup vs baseline: 1.9719x; 1.9719x over previous
#include <cuda_runtime.h>
#include <cstdint>

#define B_  8
#define C_  512
#define N_  1024
#define NH  8
#define CH  64
#define G_  32
#define CPG 16
#define EPS 1e-5f

// ---------------- static scratch ----------------
__device__ float g_hn  [(long long)B_ * C_ * N_];        // 16 MB
__device__ float g_qkv [(long long)B_ * 3 * C_ * N_];    // 48 MB
__device__ float g_att [(long long)B_ * C_ * N_];        // 16 MB
__device__ float g_proj[(long long)B_ * C_ * N_];        // 16 MB

// ---------------- mma.sync tf32 helpers (sm_80+ PTX, valid on sm_103) ----------------
__device__ __forceinline__ uint32_t f2tf(float f) {
    uint32_t u;
    asm("cvt.rna.tf32.f32 %0, %1;" : "=r"(u) : "f"(f));
    return u;
}
// D(16x8 f32) += A(16x8 tf32) * B(8x8 tf32)
// A frags: a0=(g,tig) a1=(g+8,tig) a2=(g,tig+4) a3=(g+8,tig+4)
// B frags: b0=(k=tig,n=g) b1=(k=tig+4,n=g)
// C frags: c0=(g,2tig) c1=(g,2tig+1) c2=(g+8,2tig) c3=(g+8,2tig+1)
__device__ __forceinline__ void mma8(float c[4], uint32_t a0, uint32_t a1, uint32_t a2,
                                     uint32_t a3, uint32_t b0, uint32_t b1) {
    asm volatile(
        "mma.sync.aligned.m16n8k8.row.col.f32.tf32.tf32.f32 "
        "{%0,%1,%2,%3}, {%4,%5,%6,%7}, {%8,%9}, {%0,%1,%2,%3};"
        : "+f"(c[0]), "+f"(c[1]), "+f"(c[2]), "+f"(c[3])
        : "r"(a0), "r"(a1), "r"(a2), "r"(a3), "r"(b0), "r"(b1));
}

// ---------------- dense tf32 tensor GEMM ----------------
// C[m][n] = sum_k A[m][k]*X[k][n] + bias[m];  A [M][512] lda=512, X [512][1024], C ld 1024
// CTA tile 128x128, BK=32, 8 warps (2m x 4n), warp tile 64x32 (4 m16 x 4 n8).
__global__ __launch_bounds__(256, 2) void mgemm_k(
    const float* __restrict__ A, const float* __restrict__ X,
    float* __restrict__ Cm, const float* __restrict__ bias,
    long long sX, long long sC)
{
    __shared__ uint32_t As[128][36];   // [m][k] tf32
    __shared__ uint32_t Bs[32][132];   // [k][n] tf32

    const int tid = threadIdx.x, w = tid >> 5, lane = tid & 31;
    const int g = lane >> 2, tig = lane & 3;
    const int wm = w & 1, wn = w >> 1;

    const float* Ag = A + (long long)blockIdx.y * 128 * 512;
    const float* Xg = X + blockIdx.z * sX + blockIdx.x * 128;
    float* Cg = Cm + blockIdx.z * sC + (long long)blockIdx.y * 128 * 1024 + blockIdx.x * 128;

    float acc[4][4][4];
#pragma unroll
    for (int mt = 0; mt < 4; mt++)
#pragma unroll
        for (int nt = 0; nt < 4; nt++)
#pragma unroll
            for (int i = 0; i < 4; i++) acc[mt][nt][i] = 0.f;

    for (int kb = 0; kb < 16; kb++) {
        const int k0 = kb * 32;
        __syncthreads();
        // A tile: 128x32 -> As[m][k]
#pragma unroll
        for (int p = 0; p < 4; p++) {
            int idx = tid + p * 256;
            int m = idx >> 3, j = idx & 7;
            float4 v = *(const float4*)(Ag + (long long)m * 512 + k0 + j * 4);
            uint4 u = make_uint4(f2tf(v.x), f2tf(v.y), f2tf(v.z), f2tf(v.w));
            *(uint4*)&As[m][j * 4] = u;
        }
        // B tile: 32x128 -> Bs[k][n]
#pragma unroll
        for (int p = 0; p < 4; p++) {
            int idx = tid + p * 256;
            int k = idx >> 5, j = idx & 31;
            float4 v = *(const float4*)(Xg + (long long)(k0 + k) * 1024 + j * 4);
            uint4 u = make_uint4(f2tf(v.x), f2tf(v.y), f2tf(v.z), f2tf(v.w));
            *(uint4*)&Bs[k][j * 4] = u;
        }
        __syncthreads();

#pragma unroll
        for (int ks = 0; ks < 4; ks++) {
            const int kk = ks * 8;
            uint32_t a[4][4], b[4][2];
#pragma unroll
            for (int mt = 0; mt < 4; mt++) {
                int mr = wm * 64 + mt * 16 + g;
                a[mt][0] = As[mr][kk + tig];
                a[mt][1] = As[mr + 8][kk + tig];
                a[mt][2] = As[mr][kk + tig + 4];
                a[mt][3] = As[mr + 8][kk + tig + 4];
            }
#pragma unroll
            for (int nt = 0; nt < 4; nt++) {
                int nb = wn * 32 + nt * 8 + g;
                b[nt][0] = Bs[kk + tig][nb];
                b[nt][1] = Bs[kk + tig + 4][nb];
            }
#pragma unroll
            for (int mt = 0; mt < 4; mt++)
#pragma unroll
                for (int nt = 0; nt < 4; nt++)
                    mma8(acc[mt][nt], a[mt][0], a[mt][1], a[mt][2], a[mt][3],
                         b[nt][0], b[nt][1]);
        }
    }

#pragma unroll
    for (int mt = 0; mt < 4; mt++) {
        int mr = wm * 64 + mt * 16 + g;
        float b0v = bias[blockIdx.y * 128 + mr];
        float b1v = bias[blockIdx.y * 128 + mr + 8];
#pragma unroll
        for (int nt = 0; nt < 4; nt++) {
            int nc = wn * 32 + nt * 8 + 2 * tig;
            float2 o0 = make_float2(acc[mt][nt][0] + b0v, acc[mt][nt][1] + b0v);
            float2 o1 = make_float2(acc[mt][nt][2] + b1v, acc[mt][nt][3] + b1v);
            *(float2*)(Cg + (long long)mr * 1024 + nc) = o0;
            *(float2*)(Cg + (long long)(mr + 8) * 1024 + nc) = o1;
        }
    }
}

// ---------------- flash attention with tf32 tensor MMA ----------------
// Per (b,h): q,k,v are [64][N] slices at stride 192*N (q +0, k +64N, v +128N).
// CTA: 64 t-rows, loops s in blocks of 64, d=64. 8 warps: S/O warp tile 16(m) x 32(n).
#define FST 68        // smem row stride (floats)
__global__ __launch_bounds__(256, 2) void flash_k(
    const float* __restrict__ qkv, float* __restrict__ att)
{
    extern __shared__ float fsm[];
    float* Qs = fsm;                  // [t][c] tf32 bits (Q pre-scaled by 0.125)
    float* Ks = fsm + 64 * FST;       // [c][s] tf32 bits; reused as Os[c][t] fp32 at end
    float* Ps = fsm + 2 * 64 * FST;   // [t][s] fp32 logits -> tf32 probs
    float* Vs = fsm + 3 * 64 * FST;   // [s][c] tf32 bits
    float* m_s = fsm + 4 * 64 * FST;
    float* l_s = m_s + 64;
    float* r_s = m_s + 128;
    uint32_t* Qsu = (uint32_t*)Qs;
    uint32_t* Ksu = (uint32_t*)Ks;
    uint32_t* Psu = (uint32_t*)Ps;
    uint32_t* Vsu = (uint32_t*)Vs;

    const int bh = blockIdx.y;
    const int t0 = blockIdx.x * 64;
    const float* q = qkv + (long long)bh * 192 * N_;
    const float* k = q + 64 * N_;
    const float* v = q + 128 * N_;

    const int tid = threadIdx.x, w = tid >> 5, lane = tid & 31;
    const int g = lane >> 2, tig = lane & 3;
    const int wm = w & 3, wn = w >> 2;
    const int tr = wm * 16 + g;

    // Q tile: [c][t] global -> Qs[t][c], scaled, tf32
#pragma unroll
    for (int p = 0; p < 4; p++) {
        int c = (tid >> 4) + p * 16;
        int t4 = (tid & 15) * 4;
        float4 vq = *(const float4*)(q + (long long)c * N_ + t0 + t4);
        Qsu[(t4 + 0) * FST + c] = f2tf(vq.x * 0.125f);
        Qsu[(t4 + 1) * FST + c] = f2tf(vq.y * 0.125f);
        Qsu[(t4 + 2) * FST + c] = f2tf(vq.z * 0.125f);
        Qsu[(t4 + 3) * FST + c] = f2tf(vq.w * 0.125f);
    }
    if (tid < 64) { m_s[tid] = -1e30f; l_s[tid] = 0.f; }

    float Of[4][4];
#pragma unroll
    for (int nt = 0; nt < 4; nt++)
#pragma unroll
        for (int i = 0; i < 4; i++) Of[nt][i] = 0.f;

    for (int s0 = 0; s0 < N_; s0 += 64) {
        __syncthreads();    // prior-iteration consumers done before refill
        // K -> Ks[c][s], V -> Vs[s][c] (tf32)
#pragma unroll
        for (int p = 0; p < 4; p++) {
            int c = (tid >> 4) + p * 16;
            int s4 = (tid & 15) * 4;
            float4 kv = *(const float4*)(k + (long long)c * N_ + s0 + s4);
            uint4 u = make_uint4(f2tf(kv.x), f2tf(kv.y), f2tf(kv.z), f2tf(kv.w));
            *(uint4*)&Ksu[c * FST + s4] = u;
            float4 vv = *(const float4*)(v + (long long)c * N_ + s0 + s4);
            Vsu[(s4 + 0) * FST + c] = f2tf(vv.x);
            Vsu[(s4 + 1) * FST + c] = f2tf(vv.y);
            Vsu[(s4 + 2) * FST + c] = f2tf(vv.z);
            Vsu[(s4 + 3) * FST + c] = f2tf(vv.w);
        }
        __syncthreads();

        // S = Qt * K : [t][s] fragments
        float Sf[4][4];
#pragma unroll
        for (int nt = 0; nt < 4; nt++)
#pragma unroll
            for (int i = 0; i < 4; i++) Sf[nt][i] = 0.f;
#pragma unroll
        for (int ks = 0; ks < 8; ks++) {
            const int kk = ks * 8;
            uint32_t a0 = Qsu[tr * FST + kk + tig];
            uint32_t a1 = Qsu[(tr + 8) * FST + kk + tig];
            uint32_t a2 = Qsu[tr * FST + kk + tig + 4];
            uint32_t a3 = Qsu[(tr + 8) * FST + kk + tig + 4];
#pragma unroll
            for (int nt = 0; nt < 4; nt++) {
                int nb = wn * 32 + nt * 8 + g;
                mma8(Sf[nt], a0, a1, a2, a3,
                     Ksu[(kk + tig) * FST + nb], Ksu[(kk + tig + 4) * FST + nb]);
            }
        }
        // spill S to Ps (fp32)
#pragma unroll
        for (int nt = 0; nt < 4; nt++) {
            int cb = wn * 32 + nt * 8 + 2 * tig;
            *(float2*)&Ps[tr * FST + cb]       = make_float2(Sf[nt][0], Sf[nt][1]);
            *(float2*)&Ps[(tr + 8) * FST + cb] = make_float2(Sf[nt][2], Sf[nt][3]);
        }
        __syncthreads();

        // SIMT online softmax: 4 lanes per row, 16 cols each
        {
            int r = tid >> 2, ql = tid & 3;
            float* prow = Ps + r * FST + ql * 16;
            float4 x0 = *(float4*)(prow + 0),  x1 = *(float4*)(prow + 4);
            float4 x2 = *(float4*)(prow + 8),  x3 = *(float4*)(prow + 12);
            float rm = fmaxf(fmaxf(fmaxf(x0.x, x0.y), fmaxf(x0.z, x0.w)),
                             fmaxf(fmaxf(x1.x, x1.y), fmaxf(x1.z, x1.w)));
            rm = fmaxf(rm, fmaxf(fmaxf(fmaxf(x2.x, x2.y), fmaxf(x2.z, x2.w)),
                                 fmaxf(fmaxf(x3.x, x3.y), fmaxf(x3.z, x3.w))));
            rm = fmaxf(rm, __shfl_xor_sync(0xffffffffu, rm, 1));
            rm = fmaxf(rm, __shfl_xor_sync(0xffffffffu, rm, 2));
            float mo = m_s[r];
            float mn = fmaxf(mo, rm);
            float rsc = __expf(mo - mn);
            float rs = 0.f;
            uint32_t* pu = Psu + r * FST + ql * 16;
            float xs[16] = {x0.x, x0.y, x0.z, x0.w, x1.x, x1.y, x1.z, x1.w,
                            x2.x, x2.y, x2.z, x2.w, x3.x, x3.y, x3.z, x3.w};
#pragma unroll
            for (int i = 0; i < 16; i++) {
                float pp = __expf(xs[i] - mn);
                rs += pp;
                pu[i] = f2tf(pp);
            }
            rs += __shfl_xor_sync(0xffffffffu, rs, 1);
            rs += __shfl_xor_sync(0xffffffffu, rs, 2);
            if (ql == 0) {
                l_s[r] = l_s[r] * rsc + rs;
                m_s[r] = mn;
                r_s[r] = rsc;
            }
        }
        __syncthreads();

        // rescale O, then O += P * V
        float rc0 = r_s[tr], rc1 = r_s[tr + 8];
#pragma unroll
        for (int nt = 0; nt < 4; nt++) {
            Of[nt][0] *= rc0; Of[nt][1] *= rc0;
            Of[nt][2] *= rc1; Of[nt][3] *= rc1;
        }
#pragma unroll
        for (int ks = 0; ks < 8; ks++) {
            const int kk = ks * 8;
            uint32_t a0 = Psu[tr * FST + kk + tig];
            uint32_t a1 = Psu[(tr + 8) * FST + kk + tig];
            uint32_t a2 = Psu[tr * FST + kk + tig + 4];
            uint32_t a3 = Psu[(tr + 8) * FST + kk + tig + 4];
#pragma unroll
            for (int nt = 0; nt < 4; nt++) {
                int nb = wn * 32 + nt * 8 + g;
                mma8(Of[nt], a0, a1, a2, a3,
                     Vsu[(kk + tig) * FST + nb], Vsu[(kk + tig + 4) * FST + nb]);
            }
        }
    }

    // epilogue: normalize, transpose via smem (reuse Ks as Os[c][t]), store att[c][t]
    float li0 = 1.f / l_s[tr], li1 = 1.f / l_s[tr + 8];
    __syncthreads();
#pragma unroll
    for (int nt = 0; nt < 4; nt++) {
        int cb = wn * 32 + nt * 8 + 2 * tig;
        Ks[cb * FST + tr]           = Of[nt][0] * li0;
        Ks[(cb + 1) * FST + tr]     = Of[nt][1] * li0;
        Ks[cb * FST + tr + 8]       = Of[nt][2] * li1;
        Ks[(cb + 1) * FST + tr + 8] = Of[nt][3] * li1;
    }
    __syncthreads();
    {
        int cr = tid >> 2, tq = (tid & 3) * 16;
        float* ob = att + (long long)bh * CH * N_ + (long long)cr * N_ + t0 + tq;
#pragma unroll
        for (int i = 0; i < 4; i++)
            *(float4*)(ob + i * 4) = *(float4*)&Ks[cr * FST + tq + i * 4];
    }
}

// ---------------- GroupNorm (optionally + residual) ----------------
template<bool RES>
__global__ __launch_bounds__(256) void gn_k(
    const float* __restrict__ in, const float* __restrict__ scale,
    const float* __restrict__ bias, const float* __restrict__ resid,
    float* __restrict__ out)
{
    const int bg = blockIdx.x;
    const int g  = bg % G_;
    const long long base = (long long)bg * CPG * N_;
    const float4* p = (const float4*)(in + base);
    const int tid = threadIdx.x;

    float s = 0.f, ss = 0.f;
    float4 loc[16];
#pragma unroll
    for (int qq = 0; qq < 16; qq++) {
        float4 v = p[tid + qq * 256];
        loc[qq] = v;
        s  += v.x + v.y + v.z + v.w;
        ss += v.x * v.x + v.y * v.y + v.z * v.z + v.w * v.w;
    }
#pragma unroll
    for (int off = 16; off; off >>= 1) {
        s  += __shfl_xor_sync(0xffffffffu, s,  off);
        ss += __shfl_xor_sync(0xffffffffu, ss, off);
    }
    __shared__ float sm[8], sm2[8];
    __shared__ float s_mu, s_r;
    if ((tid & 31) == 0) { sm[tid >> 5] = s; sm2[tid >> 5] = ss; }
    __syncthreads();
    if (tid == 0) {
        float ts = 0.f, tss = 0.f;
#pragma unroll
        for (int i = 0; i < 8; i++) { ts += sm[i]; tss += sm2[i]; }
        float mu  = ts / 16384.f;
        float var = tss / 16384.f - mu * mu;
        s_mu = mu;
        s_r  = rsqrtf(var + EPS);
    }
    __syncthreads();
    const float mu = s_mu, r = s_r;

#pragma unroll
    for (int qq = 0; qq < 16; qq++) {
        int idx = tid + qq * 256;
        int c   = g * CPG + (idx >> 8);
        float sc = scale[c] * r;
        float bi = bias[c] - mu * sc;
        float4 v = loc[qq], o;
        o.x = v.x * sc + bi; o.y = v.y * sc + bi;
        o.z = v.z * sc + bi; o.w = v.w * sc + bi;
        if (RES) {
            float4 rv = ((const float4*)(resid + base))[idx];
            o.x += rv.x; o.y += rv.y; o.z += rv.z; o.w += rv.w;
        }
        ((float4*)(out + base))[idx] = o;
    }
}

// ---------------- launch ----------------
extern "C" void kernel_launch(void* const* d_in, const int* in_sizes, int n_in,
                              void* d_out, int out_size)
{
    const float* x      = (const float*)d_in[0];
    const float* gn1_s  = (const float*)d_in[1];
    const float* gn1_b  = (const float*)d_in[2];
    const float* w_qkv  = (const float*)d_in[3];
    const float* b_qkv  = (const float*)d_in[4];
    const float* w_proj = (const float*)d_in[5];
    const float* b_proj = (const float*)d_in[6];
    const float* gn2_s  = (const float*)d_in[7];
    const float* gn2_b  = (const float*)d_in[8];
    float* out = (float*)d_out;

    float *hn, *qkv, *att, *proj;
    cudaGetSymbolAddress((void**)&hn,   g_hn);
    cudaGetSymbolAddress((void**)&qkv,  g_qkv);
    cudaGetSymbolAddress((void**)&att,  g_att);
    cudaGetSymbolAddress((void**)&proj, g_proj);

    const int flash_smem = (4 * 64 * FST + 192) * 4;   // 70400 B
    cudaFuncSetAttribute(flash_k, cudaFuncAttributeMaxDynamicSharedMemorySize, flash_smem);

    // 1) hn = GroupNorm(x)
    gn_k<false><<<B_ * G_, 256>>>(x, gn1_s, gn1_b, nullptr, hn);

    // 2) qkv = w_qkv . hn + b_qkv  (tf32 mma)
    mgemm_k<<<dim3(N_ / 128, 1536 / 128, B_), 256>>>(
        w_qkv, hn, qkv, b_qkv, (long long)C_ * N_, (long long)3 * C_ * N_);

    // 3) fused attention per (b,h)  (tf32 mma)
    flash_k<<<dim3(N_ / 64, B_ * NH), 256, flash_smem>>>(qkv, att);

    // 4) proj = w_proj . att + b_proj  (tf32 mma)
    mgemm_k<<<dim3(N_ / 128, C_ / 128, B_), 256>>>(
        w_proj, att, proj, b_proj, (long long)C_ * N_, (long long)C_ * N_);

    // 5) out = x + GroupNorm(proj)
    gn_k<true><<<B_ * G_, 256>>>(proj, gn2_s, gn2_b, x, out);
}

// round 7
// speedup vs baseline: 2.3413x; 1.1874x over previous
#include <cuda_runtime.h>
#include <cstdint>

#define B_  8
#define C_  512
#define N_  1024
#define NH  8
#define CH  64
#define G_  32
#define CPG 16
#define EPS 1e-5f

// ---------------- static scratch ----------------
__device__ float g_hn  [(long long)B_ * C_ * N_];        // 16 MB
__device__ float g_qkv [(long long)B_ * 3 * C_ * N_];    // 48 MB
__device__ float g_att [(long long)B_ * C_ * N_];        // 16 MB
__device__ float g_proj[(long long)B_ * C_ * N_];        // 16 MB

// ---------------- mma.sync tf32 helpers ----------------
__device__ __forceinline__ uint32_t f2tf(float f) {
    uint32_t u;
    asm("cvt.rna.tf32.f32 %0, %1;" : "=r"(u) : "f"(f));
    return u;
}
__device__ __forceinline__ float ex2f(float x) {
    float y;
    asm("ex2.approx.f32 %0, %1;" : "=f"(y) : "f"(x));
    return y;
}
// D(16x8 f32) += A(16x8 tf32, row) * B(8x8 tf32, col)
__device__ __forceinline__ void mma8(float c[4], uint32_t a0, uint32_t a1, uint32_t a2,
                                     uint32_t a3, uint32_t b0, uint32_t b1) {
    asm volatile(
        "mma.sync.aligned.m16n8k8.row.col.f32.tf32.tf32.f32 "
        "{%0,%1,%2,%3}, {%4,%5,%6,%7}, {%8,%9}, {%0,%1,%2,%3};"
        : "+f"(c[0]), "+f"(c[1]), "+f"(c[2]), "+f"(c[3])
        : "r"(a0), "r"(a1), "r"(a2), "r"(a3), "r"(b0), "r"(b1));
}

// ---------------- dense tf32 tensor GEMM (unchanged from R5 win) ----------------
__global__ __launch_bounds__(256, 2) void mgemm_k(
    const float* __restrict__ A, const float* __restrict__ X,
    float* __restrict__ Cm, const float* __restrict__ bias,
    long long sX, long long sC)
{
    __shared__ uint32_t As[128][36];
    __shared__ uint32_t Bs[32][132];

    const int tid = threadIdx.x, w = tid >> 5, lane = tid & 31;
    const int g = lane >> 2, tig = lane & 3;
    const int wm = w & 1, wn = w >> 1;

    const float* Ag = A + (long long)blockIdx.y * 128 * 512;
    const float* Xg = X + blockIdx.z * sX + blockIdx.x * 128;
    float* Cg = Cm + blockIdx.z * sC + (long long)blockIdx.y * 128 * 1024 + blockIdx.x * 128;

    float acc[4][4][4];
#pragma unroll
    for (int mt = 0; mt < 4; mt++)
#pragma unroll
        for (int nt = 0; nt < 4; nt++)
#pragma unroll
            for (int i = 0; i < 4; i++) acc[mt][nt][i] = 0.f;

    for (int kb = 0; kb < 16; kb++) {
        const int k0 = kb * 32;
        __syncthreads();
#pragma unroll
        for (int p = 0; p < 4; p++) {
            int idx = tid + p * 256;
            int m = idx >> 3, j = idx & 7;
            float4 v = *(const float4*)(Ag + (long long)m * 512 + k0 + j * 4);
            uint4 u = make_uint4(f2tf(v.x), f2tf(v.y), f2tf(v.z), f2tf(v.w));
            *(uint4*)&As[m][j * 4] = u;
        }
#pragma unroll
        for (int p = 0; p < 4; p++) {
            int idx = tid + p * 256;
            int k = idx >> 5, j = idx & 31;
            float4 v = *(const float4*)(Xg + (long long)(k0 + k) * 1024 + j * 4);
            uint4 u = make_uint4(f2tf(v.x), f2tf(v.y), f2tf(v.z), f2tf(v.w));
            *(uint4*)&Bs[k][j * 4] = u;
        }
        __syncthreads();

#pragma unroll
        for (int ks = 0; ks < 4; ks++) {
            const int kk = ks * 8;
            uint32_t a[4][4], b[4][2];
#pragma unroll
            for (int mt = 0; mt < 4; mt++) {
                int mr = wm * 64 + mt * 16 + g;
                a[mt][0] = As[mr][kk + tig];
                a[mt][1] = As[mr + 8][kk + tig];
                a[mt][2] = As[mr][kk + tig + 4];
                a[mt][3] = As[mr + 8][kk + tig + 4];
            }
#pragma unroll
            for (int nt = 0; nt < 4; nt++) {
                int nb = wn * 32 + nt * 8 + g;
                b[nt][0] = Bs[kk + tig][nb];
                b[nt][1] = Bs[kk + tig + 4][nb];
            }
#pragma unroll
            for (int mt = 0; mt < 4; mt++)
#pragma unroll
                for (int nt = 0; nt < 4; nt++)
                    mma8(acc[mt][nt], a[mt][0], a[mt][1], a[mt][2], a[mt][3],
                         b[nt][0], b[nt][1]);
        }
    }

#pragma unroll
    for (int mt = 0; mt < 4; mt++) {
        int mr = wm * 64 + mt * 16 + g;
        float b0v = bias[blockIdx.y * 128 + mr];
        float b1v = bias[blockIdx.y * 128 + mr + 8];
#pragma unroll
        for (int nt = 0; nt < 4; nt++) {
            int nc = wn * 32 + nt * 8 + 2 * tig;
            float2 o0 = make_float2(acc[mt][nt][0] + b0v, acc[mt][nt][1] + b0v);
            float2 o1 = make_float2(acc[mt][nt][2] + b1v, acc[mt][nt][3] + b1v);
            *(float2*)(Cg + (long long)mr * 1024 + nc) = o0;
            *(float2*)(Cg + (long long)(mr + 8) * 1024 + nc) = o1;
        }
    }
}

// ---------------- flash attention: register softmax, warp-owned rows ----------------
// CTA = 128 t-rows, 8 warps, warp w owns t-rows [w*16, w*16+16) across all 64 s-cols.
// smem: QP [128][FST] (Q[t][c] tf32, reused as P[t][s]); Ks [64][FST] (K[c][s]);
//       Vs [64][FST] (V[s][c]). Epilogue reuses Ks/Vs as Os[c][132].
#define FST 68
#define QSCALE 0.1803368801111204f   /* 0.125 * log2(e) */
__global__ __launch_bounds__(256, 2) void flash_k(
    const float* __restrict__ qkv, float* __restrict__ att)
{
    extern __shared__ float fsm[];
    uint32_t* QPu = (uint32_t*)fsm;
    uint32_t* Ksu = (uint32_t*)(fsm + 128 * FST);
    uint32_t* Vsu = (uint32_t*)(fsm + 192 * FST);

    const int bh = blockIdx.y;
    const int t0 = blockIdx.x * 128;
    const float* q  = qkv + (long long)bh * 192 * N_;
    const float* kg = q + 64 * N_;
    const float* vg = q + 128 * N_;

    const int tid = threadIdx.x, w = tid >> 5, lane = tid & 31;
    const int g = lane >> 2, tig = lane & 3;
    const int tr = w * 16 + g;

    // Q tile [c][t] global -> QP[t][c] tf32, scaled (one-time)
#pragma unroll
    for (int p = 0; p < 8; p++) {
        int fid = tid + p * 256;
        int c = fid >> 5, t4 = (fid & 31) * 4;
        float4 vq = *(const float4*)(q + (long long)c * N_ + t0 + t4);
        QPu[(t4 + 0) * FST + c] = f2tf(vq.x * QSCALE);
        QPu[(t4 + 1) * FST + c] = f2tf(vq.y * QSCALE);
        QPu[(t4 + 2) * FST + c] = f2tf(vq.z * QSCALE);
        QPu[(t4 + 3) * FST + c] = f2tf(vq.w * QSCALE);
    }
    __syncthreads();

    // hoist Q fragments to registers
    uint32_t qa[8][4];
#pragma unroll
    for (int ks = 0; ks < 8; ks++) {
        const int kk = ks * 8;
        qa[ks][0] = QPu[tr * FST + kk + tig];
        qa[ks][1] = QPu[(tr + 8) * FST + kk + tig];
        qa[ks][2] = QPu[tr * FST + kk + tig + 4];
        qa[ks][3] = QPu[(tr + 8) * FST + kk + tig + 4];
    }

    float of[8][4];
#pragma unroll
    for (int nt = 0; nt < 8; nt++)
#pragma unroll
        for (int i = 0; i < 4; i++) of[nt][i] = 0.f;
    float m0 = -1e30f, m1 = -1e30f, l0 = 0.f, l1 = 0.f;

    for (int s0 = 0; s0 < N_; s0 += 64) {
        __syncthreads();   // prior PV / Q-frag reads done before K/V (and P) refill
        // K -> Ks[c][s], V -> Vs[s][c] (tf32)
#pragma unroll
        for (int p = 0; p < 4; p++) {
            int c = (tid >> 4) + p * 16;
            int s4 = (tid & 15) * 4;
            float4 kv = *(const float4*)(kg + (long long)c * N_ + s0 + s4);
            uint4 u = make_uint4(f2tf(kv.x), f2tf(kv.y), f2tf(kv.z), f2tf(kv.w));
            *(uint4*)&Ksu[c * FST + s4] = u;
            float4 vv = *(const float4*)(vg + (long long)c * N_ + s0 + s4);
            Vsu[(s4 + 0) * FST + c] = f2tf(vv.x);
            Vsu[(s4 + 1) * FST + c] = f2tf(vv.y);
            Vsu[(s4 + 2) * FST + c] = f2tf(vv.z);
            Vsu[(s4 + 3) * FST + c] = f2tf(vv.w);
        }
        __syncthreads();

        // S = Q*K (16x64 per warp), accum in registers; log2-domain logits
        float sf[8][4];
#pragma unroll
        for (int nt = 0; nt < 8; nt++)
#pragma unroll
            for (int i = 0; i < 4; i++) sf[nt][i] = 0.f;
#pragma unroll
        for (int ks = 0; ks < 8; ks++) {
            const int kk = ks * 8;
#pragma unroll
            for (int nt = 0; nt < 8; nt++) {
                int nb = nt * 8 + g;
                mma8(sf[nt], qa[ks][0], qa[ks][1], qa[ks][2], qa[ks][3],
                     Ksu[(kk + tig) * FST + nb], Ksu[(kk + tig + 4) * FST + nb]);
            }
        }

        // register online softmax: row tr (frags 0,1) and row tr+8 (frags 2,3)
        float mx0 = -1e30f, mx1 = -1e30f;
#pragma unroll
        for (int nt = 0; nt < 8; nt++) {
            mx0 = fmaxf(mx0, fmaxf(sf[nt][0], sf[nt][1]));
            mx1 = fmaxf(mx1, fmaxf(sf[nt][2], sf[nt][3]));
        }
        mx0 = fmaxf(mx0, __shfl_xor_sync(0xffffffffu, mx0, 1));
        mx0 = fmaxf(mx0, __shfl_xor_sync(0xffffffffu, mx0, 2));
        mx1 = fmaxf(mx1, __shfl_xor_sync(0xffffffffu, mx1, 1));
        mx1 = fmaxf(mx1, __shfl_xor_sync(0xffffffffu, mx1, 2));
        float mn0 = fmaxf(m0, mx0), mn1 = fmaxf(m1, mx1);
        float rs0 = ex2f(m0 - mn0), rs1 = ex2f(m1 - mn1);
        float sum0 = 0.f, sum1 = 0.f;
#pragma unroll
        for (int nt = 0; nt < 8; nt++) {
            float p0 = ex2f(sf[nt][0] - mn0), p1 = ex2f(sf[nt][1] - mn0);
            float p2 = ex2f(sf[nt][2] - mn1), p3 = ex2f(sf[nt][3] - mn1);
            sum0 += p0 + p1; sum1 += p2 + p3;
            uint2 u0 = make_uint2(f2tf(p0), f2tf(p1));
            uint2 u1 = make_uint2(f2tf(p2), f2tf(p3));
            *(uint2*)&QPu[tr * FST + nt * 8 + 2 * tig] = u0;
            *(uint2*)&QPu[(tr + 8) * FST + nt * 8 + 2 * tig] = u1;
        }
        sum0 += __shfl_xor_sync(0xffffffffu, sum0, 1);
        sum0 += __shfl_xor_sync(0xffffffffu, sum0, 2);
        sum1 += __shfl_xor_sync(0xffffffffu, sum1, 1);
        sum1 += __shfl_xor_sync(0xffffffffu, sum1, 2);
        l0 = l0 * rs0 + sum0;  l1 = l1 * rs1 + sum1;
        m0 = mn0;  m1 = mn1;
#pragma unroll
        for (int nt = 0; nt < 8; nt++) {
            of[nt][0] *= rs0; of[nt][1] *= rs0;
            of[nt][2] *= rs1; of[nt][3] *= rs1;
        }
        __syncthreads();   // P visible to all lanes (A-frags read P cols owned by other lanes)

        // O += P * V
#pragma unroll
        for (int ks = 0; ks < 8; ks++) {
            const int kk = ks * 8;
            uint32_t a0 = QPu[tr * FST + kk + tig];
            uint32_t a1 = QPu[(tr + 8) * FST + kk + tig];
            uint32_t a2 = QPu[tr * FST + kk + tig + 4];
            uint32_t a3 = QPu[(tr + 8) * FST + kk + tig + 4];
#pragma unroll
            for (int nt = 0; nt < 8; nt++) {
                int nb = nt * 8 + g;
                mma8(of[nt], a0, a1, a2, a3,
                     Vsu[(kk + tig) * FST + nb], Vsu[(kk + tig + 4) * FST + nb]);
            }
        }
    }

    // epilogue: normalize, transpose via smem (Os[c][t] stride 132 over Ks/Vs region)
    float li0 = 1.f / l0, li1 = 1.f / l1;
    __syncthreads();
    float* Os = fsm + 128 * FST;
#pragma unroll
    for (int nt = 0; nt < 8; nt++) {
        int c = nt * 8 + 2 * tig;
        Os[c * 132 + tr]           = of[nt][0] * li0;
        Os[(c + 1) * 132 + tr]     = of[nt][1] * li0;
        Os[c * 132 + tr + 8]       = of[nt][2] * li1;
        Os[(c + 1) * 132 + tr + 8] = of[nt][3] * li1;
    }
    __syncthreads();
    float* ab = att + (long long)bh * CH * N_;
#pragma unroll
    for (int p = 0; p < 8; p++) {
        int fid = tid + p * 256;
        int c = fid >> 5, t4 = (fid & 31) * 4;
        *(float4*)(ab + (long long)c * N_ + t0 + t4) = *(float4*)&Os[c * 132 + t4];
    }
}

// ---------------- GroupNorm (optionally + residual) ----------------
template<bool RES>
__global__ __launch_bounds__(256) void gn_k(
    const float* __restrict__ in, const float* __restrict__ scale,
    const float* __restrict__ bias, const float* __restrict__ resid,
    float* __restrict__ out)
{
    const int bg = blockIdx.x;
    const int g  = bg % G_;
    const long long base = (long long)bg * CPG * N_;
    const float4* p = (const float4*)(in + base);
    const int tid = threadIdx.x;

    float s = 0.f, ss = 0.f;
    float4 loc[16];
#pragma unroll
    for (int qq = 0; qq < 16; qq++) {
        float4 v = p[tid + qq * 256];
        loc[qq] = v;
        s  += v.x + v.y + v.z + v.w;
        ss += v.x * v.x + v.y * v.y + v.z * v.z + v.w * v.w;
    }
#pragma unroll
    for (int off = 16; off; off >>= 1) {
        s  += __shfl_xor_sync(0xffffffffu, s,  off);
        ss += __shfl_xor_sync(0xffffffffu, ss, off);
    }
    __shared__ float sm[8], sm2[8];
    __shared__ float s_mu, s_r;
    if ((tid & 31) == 0) { sm[tid >> 5] = s; sm2[tid >> 5] = ss; }
    __syncthreads();
    if (tid == 0) {
        float ts = 0.f, tss = 0.f;
#pragma unroll
        for (int i = 0; i < 8; i++) { ts += sm[i]; tss += sm2[i]; }
        float mu  = ts / 16384.f;
        float var = tss / 16384.f - mu * mu;
        s_mu = mu;
        s_r  = rsqrtf(var + EPS);
    }
    __syncthreads();
    const float mu = s_mu, r = s_r;

#pragma unroll
    for (int qq = 0; qq < 16; qq++) {
        int idx = tid + qq * 256;
        int c   = g * CPG + (idx >> 8);
        float sc = scale[c] * r;
        float bi = bias[c] - mu * sc;
        float4 v = loc[qq], o;
        o.x = v.x * sc + bi; o.y = v.y * sc + bi;
        o.z = v.z * sc + bi; o.w = v.w * sc + bi;
        if (RES) {
            float4 rv = ((const float4*)(resid + base))[idx];
            o.x += rv.x; o.y += rv.y; o.z += rv.z; o.w += rv.w;
        }
        ((float4*)(out + base))[idx] = o;
    }
}

// ---------------- launch ----------------
extern "C" void kernel_launch(void* const* d_in, const int* in_sizes, int n_in,
                              void* d_out, int out_size)
{
    const float* x      = (const float*)d_in[0];
    const float* gn1_s  = (const float*)d_in[1];
    const float* gn1_b  = (const float*)d_in[2];
    const float* w_qkv  = (const float*)d_in[3];
    const float* b_qkv  = (const float*)d_in[4];
    const float* w_proj = (const float*)d_in[5];
    const float* b_proj = (const float*)d_in[6];
    const float* gn2_s  = (const float*)d_in[7];
    const float* gn2_b  = (const float*)d_in[8];
    float* out = (float*)d_out;

    float *hn, *qkv, *att, *proj;
    cudaGetSymbolAddress((void**)&hn,   g_hn);
    cudaGetSymbolAddress((void**)&qkv,  g_qkv);
    cudaGetSymbolAddress((void**)&att,  g_att);
    cudaGetSymbolAddress((void**)&proj, g_proj);

    const int flash_smem = 256 * FST * 4;   // 69632 B
    cudaFuncSetAttribute(flash_k, cudaFuncAttributeMaxDynamicSharedMemorySize, flash_smem);

    // 1) hn = GroupNorm(x)
    gn_k<false><<<B_ * G_, 256>>>(x, gn1_s, gn1_b, nullptr, hn);

    // 2) qkv = w_qkv . hn + b_qkv  (tf32 mma)
    mgemm_k<<<dim3(N_ / 128, 1536 / 128, B_), 256>>>(
        w_qkv, hn, qkv, b_qkv, (long long)C_ * N_, (long long)3 * C_ * N_);

    // 3) fused attention per (b,h)  (tf32 mma, register softmax)
    flash_k<<<dim3(N_ / 128, B_ * NH), 256, flash_smem>>>(qkv, att);

    // 4) proj = w_proj . att + b_proj  (tf32 mma)
    mgemm_k<<<dim3(N_ / 128, C_ / 128, B_), 256>>>(
        w_proj, att, proj, b_proj, (long long)C_ * N_, (long long)C_ * N_);

    // 5) out = x + GroupNorm(proj)
    gn_k<true><<<B_ * G_, 256>>>(proj, gn2_s, gn2_b, x, out);
}